// round 6
// baseline (speedup 1.0000x reference)
#include <cuda_runtime.h>
#include <cuda_bf16.h>
#include <cstdint>

#define NROWS  8192
#define HALF_N 4096
#define D      256
#define MT     128            // rows per CTA
#define NT     128            // cols per tile
#define TIL    32             // 4096 / NT tiles per CTA (one col-half)
#define THREADS 256

// fp8 tiles: rows are 256 B. A tile 32KB @0, B buf0 @32768, B buf1 @65536
#define SM_A  0
#define SM_B0 32768
#define SMEM_TOTAL (3 * 32768)

__device__ uint8_t g_zq[NROWS * D];         // normalized rows, e4m3 (2 MB)
__device__ float g_part[NROWS * 2];         // per-row exp-sum partial per col-half
__device__ float g_pos[NROWS];              // per-row positive logit

// ---------------------------------------------------------------------------
__device__ __forceinline__ uint32_t smem_u32(const void* p) {
    uint32_t a;
    asm("{ .reg .u64 t; cvta.to.shared.u64 t, %1; cvt.u32.u64 %0, t; }" : "=r"(a) : "l"(p));
    return a;
}
__device__ __forceinline__ void cp16(uint32_t dst, const void* src) {
    asm volatile("cp.async.cg.shared.global [%0], [%1], 16;" :: "r"(dst), "l"(src) : "memory");
}
#define CP_COMMIT() asm volatile("cp.async.commit_group;" ::: "memory")
#define CP_WAIT(n)  asm volatile("cp.async.wait_group %0;" :: "n"(n) : "memory")

__device__ __forceinline__ void ldsm4(uint32_t* r, uint32_t addr) {
    asm volatile("ldmatrix.sync.aligned.m8n8.x4.shared.b16 {%0,%1,%2,%3}, [%4];"
        : "=r"(r[0]), "=r"(r[1]), "=r"(r[2]), "=r"(r[3]) : "r"(addr));
}
// fp8 e4m3 mma: D[16x8] += A[16x32] * B[32x8]
__device__ __forceinline__ void mma_fp8(float* c, const uint32_t* a,
                                        uint32_t b0, uint32_t b1) {
    asm volatile("mma.sync.aligned.m16n8k32.row.col.f32.e4m3.e4m3.f32 "
        "{%0,%1,%2,%3}, {%4,%5,%6,%7}, {%8,%9}, {%0,%1,%2,%3};"
        : "+f"(c[0]), "+f"(c[1]), "+f"(c[2]), "+f"(c[3])
        : "r"(a[0]), "r"(a[1]), "r"(a[2]), "r"(a[3]), "r"(b0), "r"(b1));
}
// pack 4 floats -> 4 e4m3 bytes (low..high = x,y,z,w)
__device__ __forceinline__ uint32_t pack_e4m3x4(float x, float y, float z, float w) {
    uint16_t lo, hi;
    asm("cvt.rn.satfinite.e4m3x2.f32 %0, %1, %2;" : "=h"(lo) : "f"(y), "f"(x));
    asm("cvt.rn.satfinite.e4m3x2.f32 %0, %1, %2;" : "=h"(hi) : "f"(w), "f"(z));
    return (uint32_t)lo | ((uint32_t)hi << 16);
}

// ---------------------------------------------------------------------------
// Kernel 1: L2-normalize rows -> e4m3. One warp per row.
// ---------------------------------------------------------------------------
__global__ void __launch_bounds__(256) norm_kernel(const float* __restrict__ z1,
                                                   const float* __restrict__ z2) {
    int wid = threadIdx.x >> 5, lid = threadIdx.x & 31;
    int row = blockIdx.x * 8 + wid;
    const float* src = (row < HALF_N) ? z1 + (size_t)row * D
                                      : z2 + (size_t)(row - HALF_N) * D;
    const float4* s4 = (const float4*)src;
    float4 a = s4[lid], b = s4[lid + 32];
    float ss = a.x*a.x + a.y*a.y + a.z*a.z + a.w*a.w
             + b.x*b.x + b.y*b.y + b.z*b.z + b.w*b.w;
    #pragma unroll
    for (int o = 16; o > 0; o >>= 1) ss += __shfl_xor_sync(0xffffffffu, ss, o);
    float inv = 1.0f / fmaxf(sqrtf(ss), 1e-8f);
    uint32_t* dst = (uint32_t*)(g_zq + (size_t)row * D);
    dst[lid]      = pack_e4m3x4(a.x*inv, a.y*inv, a.z*inv, a.w*inv);
    dst[lid + 32] = pack_e4m3x4(b.x*inv, b.y*inv, b.z*inv, b.w*inv);
}

// ---------------------------------------------------------------------------
// Kernel 2: fp8 mma.sync sim GEMM + fused exp/row-sum epilogue in registers.
// Grid 128 = 64 row-blocks x 2 col-halves. 8 warps; warp tile m32 x n64.
// K = 256 fp8 = 8 k-steps of 32.
// ---------------------------------------------------------------------------
__global__ void __launch_bounds__(THREADS, 1) sim_kernel() {
    extern __shared__ char smem[];
    __shared__ float rowsum[MT];
    uint32_t sb = smem_u32(smem);

    int tid = threadIdx.x, wid = tid >> 5, lane = tid & 31;
    int rb = blockIdx.x >> 1, half = blockIdx.x & 1;
    int rgw = wid & 3;          // warp row-group: rows rgw*32 .. +31
    int cg  = wid >> 2;         // warp col-group: cols cg*64 .. +63

    if (tid < MT) rowsum[tid] = 0.0f;

    const char* gA = (const char*)(g_zq + (size_t)rb * MT * D);
    const char* gB = (const char*)(g_zq + (size_t)half * HALF_N * D);

    // ---- prologue: A (2048 chunks of 16B) + B tiles 0,1
    #pragma unroll
    for (int i = 0; i < 8; i++) {
        uint32_t c = i * 256 + tid, r = c >> 4, ch = c & 15;
        cp16(sb + SM_A + r * 256 + ((ch ^ (r & 7)) << 4), gA + (size_t)c * 16);
    }
    #pragma unroll
    for (int i = 0; i < 8; i++) {
        uint32_t c = i * 256 + tid, r = c >> 4, ch = c & 15;
        cp16(sb + SM_B0 + r * 256 + ((ch ^ (r & 7)) << 4), gB + (size_t)c * 16);
    }
    CP_COMMIT();                                 // g0 = A + B0
    #pragma unroll
    for (int i = 0; i < 8; i++) {
        uint32_t c = i * 256 + tid, r = c >> 4, ch = c & 15;
        cp16(sb + SM_B0 + 32768 + r * 256 + ((ch ^ (r & 7)) << 4),
             gB + 32768 + (size_t)c * 16);
    }
    CP_COMMIT();                                 // g1 = B1

    // ---- per-lane ldsm addressing (fp8 m16n8k32 fragment order)
    // lanes 0-7: m0 rows 0-7 b0-15 | 8-15: m1 rows 8-15 b0-15
    // 16-23: m2 rows 0-7 b16-31    | 24-31: m3 rows 8-15 b16-31
    uint32_t mm = lane >> 3, rr = lane & 7;
    uint32_t rsel  = (mm & 1) * 8 + rr;          // row within 16-row block
    uint32_t cbase = mm >> 1;                    // chunk +0 / +1
    uint32_t aRow0 = rgw * 32 + rsel, aRow1 = aRow0 + 16;
    uint32_t aBase0 = sb + SM_A + aRow0 * 256, aSwz0 = aRow0 & 7;
    uint32_t aBase1 = sb + SM_A + aRow1 * 256, aSwz1 = aRow1 & 7;
    uint32_t bRow[4], bSwz[4];
    #pragma unroll
    for (int q = 0; q < 4; q++) {
        uint32_t br = cg * 64 + q * 16 + rsel;
        bRow[q] = br * 256; bSwz[q] = br & 7;
    }

    // ---- epilogue identity (C fragment layout identical to bf16 case)
    int rlocBase = rgw * 32 + (lane >> 2);
    int giBase   = rb * MT + rlocBase;
    int colBase  = half * HALF_N + cg * 64 + ((lane & 3) << 1);
    int js       = rb & 31;                      // the one special tile
    bool diagCta = (half == (rb >> 5));

    float rsum[2][2] = {{0.f, 0.f}, {0.f, 0.f}};

    for (int j = 0; j < TIL; j++) {
        if (j == TIL - 1) { CP_WAIT(0); } else { CP_WAIT(1); }
        __syncthreads();
        uint32_t bBuf = sb + SM_B0 + (uint32_t)(j & 1) * 32768;

        float acc[2][8][4];
        #pragma unroll
        for (int rg = 0; rg < 2; rg++)
            #pragma unroll
            for (int nb = 0; nb < 8; nb++)
                #pragma unroll
                for (int e = 0; e < 4; e++) acc[rg][nb][e] = 0.f;

        #pragma unroll
        for (int k = 0; k < 8; k++) {            // k-step of 32 fp8 = 2 chunks
            uint32_t ch = 2 * k + cbase;
            uint32_t a0[4], a1[4], b[4][4];
            ldsm4(a0, aBase0 + ((ch ^ aSwz0) << 4));
            ldsm4(a1, aBase1 + ((ch ^ aSwz1) << 4));
            #pragma unroll
            for (int q = 0; q < 4; q++)
                ldsm4(b[q], bBuf + bRow[q] + ((ch ^ bSwz[q]) << 4));
            #pragma unroll
            for (int q = 0; q < 4; q++) {
                mma_fp8(acc[0][2*q],   a0, b[q][0], b[q][2]);
                mma_fp8(acc[0][2*q+1], a0, b[q][1], b[q][3]);
                mma_fp8(acc[1][2*q],   a1, b[q][0], b[q][2]);
                mma_fp8(acc[1][2*q+1], a1, b[q][1], b[q][3]);
            }
        }

        __syncthreads();                         // all warps done reading bBuf
        if (j + 2 < TIL) {                       // prefetch tile j+2 into bBuf
            const char* src = gB + (size_t)(j + 2) * 32768;
            #pragma unroll
            for (int i = 0; i < 8; i++) {
                uint32_t c = i * 256 + tid, r = c >> 4, ch = c & 15;
                cp16(bBuf + r * 256 + ((ch ^ (r & 7)) << 4), src + (size_t)c * 16);
            }
            CP_COMMIT();
        }

        // ---- fused epilogue on register fragments
        if (j != js) {
            #pragma unroll
            for (int rg = 0; rg < 2; rg++)
                #pragma unroll
                for (int nb = 0; nb < 8; nb++)
                    #pragma unroll
                    for (int e2 = 0; e2 < 4; e2++)
                        rsum[rg][e2 >> 1] += __expf(2.f * acc[rg][nb][e2]);
        } else {
            #pragma unroll
            for (int rg = 0; rg < 2; rg++) {
                #pragma unroll
                for (int e2 = 0; e2 < 4; e2++) {
                    int h = e2 >> 1;
                    int gi = giBase + rg * 16 + 8 * h;
                    int gtgt = diagCta ? gi
                                       : ((gi < HALF_N) ? gi + HALF_N : gi - HALF_N);
                    #pragma unroll
                    for (int nb = 0; nb < 8; nb++) {
                        float sim = 2.f * acc[rg][nb][e2];
                        int gj = colBase + j * NT + nb * 8 + (e2 & 1);
                        if (diagCta) {
                            if (gj != gtgt) rsum[rg][h] += __expf(sim);
                        } else {
                            rsum[rg][h] += __expf(sim);
                            if (gj == gtgt) g_pos[gi] = sim;
                        }
                    }
                }
            }
        }
    }

    // ---- reduce 4 lanes sharing the same rows, combine col-groups via smem
    #pragma unroll
    for (int rg = 0; rg < 2; rg++)
        #pragma unroll
        for (int h = 0; h < 2; h++) {
            float v = rsum[rg][h];
            v += __shfl_xor_sync(0xffffffffu, v, 1);
            v += __shfl_xor_sync(0xffffffffu, v, 2);
            if ((lane & 3) == 0)
                atomicAdd(&rowsum[rlocBase + rg * 16 + 8 * h], v);
        }
    __syncthreads();
    if (tid < MT)
        g_part[(size_t)(rb * MT + tid) * 2 + half] = rowsum[tid];
}

// ---------------------------------------------------------------------------
// Kernel 3: combine partials -> mean loss.
// ---------------------------------------------------------------------------
__global__ void reduce_kernel(float* __restrict__ out) {
    __shared__ float red[256];
    int t = threadIdx.x;
    float s = 0.0f;
    for (int i = t; i < NROWS; i += 256)
        s += logf(g_part[2*i] + g_part[2*i + 1]) - g_pos[i];
    red[t] = s;
    __syncthreads();
    #pragma unroll
    for (int k = 128; k > 0; k >>= 1) {
        if (t < k) red[t] += red[t + k];
        __syncthreads();
    }
    if (t == 0) out[0] = red[0] / (float)NROWS;
}

// ---------------------------------------------------------------------------
extern "C" void kernel_launch(void* const* d_in, const int* in_sizes, int n_in,
                              void* d_out, int out_size) {
    const float* z1 = (const float*)d_in[0];
    const float* z2 = (const float*)d_in[1];
    float* out = (float*)d_out;

    cudaFuncSetAttribute(sim_kernel,
                         cudaFuncAttributeMaxDynamicSharedMemorySize, SMEM_TOTAL);

    norm_kernel<<<NROWS / 8, 256>>>(z1, z2);
    sim_kernel<<<128, THREADS, SMEM_TOTAL>>>();
    reduce_kernel<<<1, 256>>>(out);
}

// round 7
// speedup vs baseline: 1.0448x; 1.0448x over previous
#include <cuda_runtime.h>
#include <cuda_bf16.h>
#include <cstdint>

#define NROWS  8192
#define HALF_N 4096
#define D      256
#define MT     128            // rows per CTA
#define NT     128            // cols per tile
#define QCOLS  2048           // cols per CTA (quarter)
#define TIL    16             // QCOLS / NT
#define THREADS 256

// fp8 tiles: rows are 256 B. A tile 32KB @0, B buf0 @32768, B buf1 @65536
#define SM_A  0
#define SM_B0 32768
#define SMEM_TOTAL (3 * 32768)

__device__ uint8_t g_zq[NROWS * D];         // normalized rows, e4m3 (2 MB)
__device__ float g_part[NROWS * 4];         // per-row exp-sum partial per quarter
__device__ float g_pos[NROWS];              // per-row positive logit

// ---------------------------------------------------------------------------
__device__ __forceinline__ uint32_t smem_u32(const void* p) {
    uint32_t a;
    asm("{ .reg .u64 t; cvta.to.shared.u64 t, %1; cvt.u32.u64 %0, t; }" : "=r"(a) : "l"(p));
    return a;
}
__device__ __forceinline__ void cp16(uint32_t dst, const void* src) {
    asm volatile("cp.async.cg.shared.global [%0], [%1], 16;" :: "r"(dst), "l"(src) : "memory");
}
#define CP_COMMIT() asm volatile("cp.async.commit_group;" ::: "memory")
#define CP_WAIT(n)  asm volatile("cp.async.wait_group %0;" :: "n"(n) : "memory")

__device__ __forceinline__ void ldsm4(uint32_t* r, uint32_t addr) {
    asm volatile("ldmatrix.sync.aligned.m8n8.x4.shared.b16 {%0,%1,%2,%3}, [%4];"
        : "=r"(r[0]), "=r"(r[1]), "=r"(r[2]), "=r"(r[3]) : "r"(addr));
}
// fp8 e4m3 mma: D[16x8] += A[16x32] * B[32x8]
__device__ __forceinline__ void mma_fp8(float* c, const uint32_t* a,
                                        uint32_t b0, uint32_t b1) {
    asm volatile("mma.sync.aligned.m16n8k32.row.col.f32.e4m3.e4m3.f32 "
        "{%0,%1,%2,%3}, {%4,%5,%6,%7}, {%8,%9}, {%0,%1,%2,%3};"
        : "+f"(c[0]), "+f"(c[1]), "+f"(c[2]), "+f"(c[3])
        : "r"(a[0]), "r"(a[1]), "r"(a[2]), "r"(a[3]), "r"(b0), "r"(b1));
}
__device__ __forceinline__ uint32_t pack_e4m3x4(float x, float y, float z, float w) {
    uint16_t lo, hi;
    asm("cvt.rn.satfinite.e4m3x2.f32 %0, %1, %2;" : "=h"(lo) : "f"(y), "f"(x));
    asm("cvt.rn.satfinite.e4m3x2.f32 %0, %1, %2;" : "=h"(hi) : "f"(w), "f"(z));
    return (uint32_t)lo | ((uint32_t)hi << 16);
}

// ---------------------------------------------------------------------------
// Kernel 1: L2-normalize rows -> e4m3. One warp per row.
// ---------------------------------------------------------------------------
__global__ void __launch_bounds__(256) norm_kernel(const float* __restrict__ z1,
                                                   const float* __restrict__ z2) {
    int wid = threadIdx.x >> 5, lid = threadIdx.x & 31;
    int row = blockIdx.x * 8 + wid;
    const float* src = (row < HALF_N) ? z1 + (size_t)row * D
                                      : z2 + (size_t)(row - HALF_N) * D;
    const float4* s4 = (const float4*)src;
    float4 a = s4[lid], b = s4[lid + 32];
    float ss = a.x*a.x + a.y*a.y + a.z*a.z + a.w*a.w
             + b.x*b.x + b.y*b.y + b.z*b.z + b.w*b.w;
    #pragma unroll
    for (int o = 16; o > 0; o >>= 1) ss += __shfl_xor_sync(0xffffffffu, ss, o);
    float inv = 1.0f / fmaxf(sqrtf(ss), 1e-8f);
    uint32_t* dst = (uint32_t*)(g_zq + (size_t)row * D);
    dst[lid]      = pack_e4m3x4(a.x*inv, a.y*inv, a.z*inv, a.w*inv);
    dst[lid + 32] = pack_e4m3x4(b.x*inv, b.y*inv, b.z*inv, b.w*inv);
}

// ---------------------------------------------------------------------------
// Kernel 2: fp8 mma.sync sim GEMM + fused exp/row-sum epilogue.
// Grid 256 = 64 row-blocks x 4 col-quarters; 2 CTAs/SM for latency hiding.
// 8 warps; warp tile m32 x n64. K = 256 fp8 = 8 k-steps of 32.
// ---------------------------------------------------------------------------
__global__ void __launch_bounds__(THREADS, 2) sim_kernel() {
    extern __shared__ char smem[];
    __shared__ float rowsum[MT];
    uint32_t sb = smem_u32(smem);

    int tid = threadIdx.x, wid = tid >> 5, lane = tid & 31;
    int rb = blockIdx.x >> 2, cq = blockIdx.x & 3;
    int rgw = wid & 3;          // warp row-group: rows rgw*32 .. +31
    int cg  = wid >> 2;         // warp col-group: cols cg*64 .. +63

    if (tid < MT) rowsum[tid] = 0.0f;

    const char* gA = (const char*)(g_zq + (size_t)rb * MT * D);
    const char* gB = (const char*)(g_zq + (size_t)cq * QCOLS * D);

    // ---- prologue: A (2048 chunks of 16B) + B tiles 0,1
    #pragma unroll
    for (int i = 0; i < 8; i++) {
        uint32_t c = i * 256 + tid, r = c >> 4, ch = c & 15;
        cp16(sb + SM_A + r * 256 + ((ch ^ (r & 7)) << 4), gA + (size_t)c * 16);
    }
    #pragma unroll
    for (int i = 0; i < 8; i++) {
        uint32_t c = i * 256 + tid, r = c >> 4, ch = c & 15;
        cp16(sb + SM_B0 + r * 256 + ((ch ^ (r & 7)) << 4), gB + (size_t)c * 16);
    }
    CP_COMMIT();                                 // g0 = A + B0
    #pragma unroll
    for (int i = 0; i < 8; i++) {
        uint32_t c = i * 256 + tid, r = c >> 4, ch = c & 15;
        cp16(sb + SM_B0 + 32768 + r * 256 + ((ch ^ (r & 7)) << 4),
             gB + 32768 + (size_t)c * 16);
    }
    CP_COMMIT();                                 // g1 = B1

    // ---- per-lane ldsm addressing (fp8 m16n8k32 fragment order)
    uint32_t mm = lane >> 3, rr = lane & 7;
    uint32_t rsel  = (mm & 1) * 8 + rr;
    uint32_t cbase = mm >> 1;
    uint32_t aRow0 = rgw * 32 + rsel, aRow1 = aRow0 + 16;
    uint32_t aBase0 = sb + SM_A + aRow0 * 256, aSwz0 = aRow0 & 7;
    uint32_t aBase1 = sb + SM_A + aRow1 * 256, aSwz1 = aRow1 & 7;
    uint32_t bRow[4], bSwz[4];
    #pragma unroll
    for (int q = 0; q < 4; q++) {
        uint32_t br = cg * 64 + q * 16 + rsel;
        bRow[q] = br * 256; bSwz[q] = br & 7;
    }

    // ---- epilogue identity
    int rlocBase = rgw * 32 + (lane >> 2);
    int giBase   = rb * MT + rlocBase;
    int colBase  = cq * QCOLS + cg * 64 + ((lane & 3) << 1);
    int qd = rb >> 4;                            // quarter holding the diagonal
    bool diagCta = (cq == qd);
    bool posCta  = (cq == (qd ^ 2));
    int js = (diagCta || posCta) ? (rb & 15) : -1;  // the one special tile

    float rsum[2][2] = {{0.f, 0.f}, {0.f, 0.f}};

    for (int j = 0; j < TIL; j++) {
        if (j == TIL - 1) { CP_WAIT(0); } else { CP_WAIT(1); }
        __syncthreads();
        uint32_t bBuf = sb + SM_B0 + (uint32_t)(j & 1) * 32768;

        float acc[2][8][4];
        #pragma unroll
        for (int rg = 0; rg < 2; rg++)
            #pragma unroll
            for (int nb = 0; nb < 8; nb++)
                #pragma unroll
                for (int e = 0; e < 4; e++) acc[rg][nb][e] = 0.f;

        #pragma unroll
        for (int k = 0; k < 8; k++) {
            uint32_t ch = 2 * k + cbase;
            uint32_t a0[4], a1[4], b[4][4];
            ldsm4(a0, aBase0 + ((ch ^ aSwz0) << 4));
            ldsm4(a1, aBase1 + ((ch ^ aSwz1) << 4));
            #pragma unroll
            for (int q = 0; q < 4; q++)
                ldsm4(b[q], bBuf + bRow[q] + ((ch ^ bSwz[q]) << 4));
            #pragma unroll
            for (int q = 0; q < 4; q++) {
                mma_fp8(acc[0][2*q],   a0, b[q][0], b[q][2]);
                mma_fp8(acc[0][2*q+1], a0, b[q][1], b[q][3]);
                mma_fp8(acc[1][2*q],   a1, b[q][0], b[q][2]);
                mma_fp8(acc[1][2*q+1], a1, b[q][1], b[q][3]);
            }
        }

        __syncthreads();                         // all warps done reading bBuf
        if (j + 2 < TIL) {                       // prefetch tile j+2 into bBuf
            const char* src = gB + (size_t)(j + 2) * 32768;
            #pragma unroll
            for (int i = 0; i < 8; i++) {
                uint32_t c = i * 256 + tid, r = c >> 4, ch = c & 15;
                cp16(bBuf + r * 256 + ((ch ^ (r & 7)) << 4), src + (size_t)c * 16);
            }
            CP_COMMIT();
        }

        // ---- fused epilogue on register fragments
        if (j != js) {
            #pragma unroll
            for (int rg = 0; rg < 2; rg++)
                #pragma unroll
                for (int nb = 0; nb < 8; nb++)
                    #pragma unroll
                    for (int e2 = 0; e2 < 4; e2++)
                        rsum[rg][e2 >> 1] += __expf(2.f * acc[rg][nb][e2]);
        } else {
            #pragma unroll
            for (int rg = 0; rg < 2; rg++) {
                #pragma unroll
                for (int e2 = 0; e2 < 4; e2++) {
                    int h = e2 >> 1;
                    int gi = giBase + rg * 16 + 8 * h;
                    int gtgt = diagCta ? gi
                                       : ((gi < HALF_N) ? gi + HALF_N : gi - HALF_N);
                    #pragma unroll
                    for (int nb = 0; nb < 8; nb++) {
                        float sim = 2.f * acc[rg][nb][e2];
                        int gj = colBase + j * NT + nb * 8 + (e2 & 1);
                        if (diagCta) {
                            if (gj != gtgt) rsum[rg][h] += __expf(sim);
                        } else {
                            rsum[rg][h] += __expf(sim);
                            if (gj == gtgt) g_pos[gi] = sim;
                        }
                    }
                }
            }
        }
    }

    // ---- reduce 4 lanes sharing the same rows, combine col-groups via smem
    #pragma unroll
    for (int rg = 0; rg < 2; rg++)
        #pragma unroll
        for (int h = 0; h < 2; h++) {
            float v = rsum[rg][h];
            v += __shfl_xor_sync(0xffffffffu, v, 1);
            v += __shfl_xor_sync(0xffffffffu, v, 2);
            if ((lane & 3) == 0)
                atomicAdd(&rowsum[rlocBase + rg * 16 + 8 * h], v);
        }
    __syncthreads();
    if (tid < MT)
        g_part[(size_t)(rb * MT + tid) * 4 + cq] = rowsum[tid];
}

// ---------------------------------------------------------------------------
// Kernel 3: combine quarter partials -> mean loss.
// ---------------------------------------------------------------------------
__global__ void reduce_kernel(float* __restrict__ out) {
    __shared__ float red[256];
    int t = threadIdx.x;
    float s = 0.0f;
    for (int i = t; i < NROWS; i += 256)
        s += logf(g_part[4*i] + g_part[4*i+1] + g_part[4*i+2] + g_part[4*i+3])
             - g_pos[i];
    red[t] = s;
    __syncthreads();
    #pragma unroll
    for (int k = 128; k > 0; k >>= 1) {
        if (t < k) red[t] += red[t + k];
        __syncthreads();
    }
    if (t == 0) out[0] = red[0] / (float)NROWS;
}

// ---------------------------------------------------------------------------
extern "C" void kernel_launch(void* const* d_in, const int* in_sizes, int n_in,
                              void* d_out, int out_size) {
    const float* z1 = (const float*)d_in[0];
    const float* z2 = (const float*)d_in[1];
    float* out = (float*)d_out;

    cudaFuncSetAttribute(sim_kernel,
                         cudaFuncAttributeMaxDynamicSharedMemorySize, SMEM_TOTAL);

    norm_kernel<<<NROWS / 8, 256>>>(z1, z2);
    sim_kernel<<<256, THREADS, SMEM_TOTAL>>>();
    reduce_kernel<<<1, 256>>>(out);
}

// round 8
// speedup vs baseline: 1.9585x; 1.8745x over previous
#include <cuda_runtime.h>
#include <cuda_bf16.h>
#include <cstdint>

#define NROWS  8192
#define HALF_N 4096
#define D      256
#define MT     128
#define NTILES 2080           // 64*65/2 upper-triangular block pairs
#define THREADS 256

// fp8 panels: 128 rows x 256 B. A @0, B @32768.
#define SM_A  0
#define SM_B  32768
#define SMEM_TOTAL 65536

__device__ uint8_t g_zq[NROWS * D];   // normalized rows, e4m3 (2 MB, L2-resident)
__device__ float g_part[NROWS];       // per-row exp-sum (diagonal excluded), atomically accumulated
__device__ float g_pos[NROWS];        // per-row positive-pair logit
__device__ float g_blk[32];           // reduce stage-1 partials

// ---------------------------------------------------------------------------
__device__ __forceinline__ uint32_t smem_u32(const void* p) {
    uint32_t a;
    asm("{ .reg .u64 t; cvta.to.shared.u64 t, %1; cvt.u32.u64 %0, t; }" : "=r"(a) : "l"(p));
    return a;
}
__device__ __forceinline__ void cp16(uint32_t dst, const void* src) {
    asm volatile("cp.async.cg.shared.global [%0], [%1], 16;" :: "r"(dst), "l"(src) : "memory");
}
#define CP_COMMIT() asm volatile("cp.async.commit_group;" ::: "memory")
#define CP_WAIT0()  asm volatile("cp.async.wait_group 0;" ::: "memory")

__device__ __forceinline__ void ldsm4(uint32_t* r, uint32_t addr) {
    asm volatile("ldmatrix.sync.aligned.m8n8.x4.shared.b16 {%0,%1,%2,%3}, [%4];"
        : "=r"(r[0]), "=r"(r[1]), "=r"(r[2]), "=r"(r[3]) : "r"(addr));
}
__device__ __forceinline__ void mma_fp8(float* c, const uint32_t* a,
                                        uint32_t b0, uint32_t b1) {
    asm volatile("mma.sync.aligned.m16n8k32.row.col.f32.e4m3.e4m3.f32 "
        "{%0,%1,%2,%3}, {%4,%5,%6,%7}, {%8,%9}, {%0,%1,%2,%3};"
        : "+f"(c[0]), "+f"(c[1]), "+f"(c[2]), "+f"(c[3])
        : "r"(a[0]), "r"(a[1]), "r"(a[2]), "r"(a[3]), "r"(b0), "r"(b1));
}
__device__ __forceinline__ uint32_t pack_e4m3x4(float x, float y, float z, float w) {
    uint16_t lo, hi;
    asm("cvt.rn.satfinite.e4m3x2.f32 %0, %1, %2;" : "=h"(lo) : "f"(y), "f"(x));
    asm("cvt.rn.satfinite.e4m3x2.f32 %0, %1, %2;" : "=h"(hi) : "f"(w), "f"(z));
    return (uint32_t)lo | ((uint32_t)hi << 16);
}

// ---------------------------------------------------------------------------
// Kernel 1: L2-normalize rows -> e4m3; also zero the accumulators.
// ---------------------------------------------------------------------------
__global__ void __launch_bounds__(256) norm_kernel(const float* __restrict__ z1,
                                                   const float* __restrict__ z2) {
    if (blockIdx.x < 32) {                       // zero g_part / g_pos (8192 each)
        int idx = blockIdx.x * 256 + threadIdx.x;
        g_part[idx] = 0.f; g_pos[idx] = 0.f;
    }
    int wid = threadIdx.x >> 5, lid = threadIdx.x & 31;
    int row = blockIdx.x * 8 + wid;
    const float* src = (row < HALF_N) ? z1 + (size_t)row * D
                                      : z2 + (size_t)(row - HALF_N) * D;
    const float4* s4 = (const float4*)src;
    float4 a = s4[lid], b = s4[lid + 32];
    float ss = a.x*a.x + a.y*a.y + a.z*a.z + a.w*a.w
             + b.x*b.x + b.y*b.y + b.z*b.z + b.w*b.w;
    #pragma unroll
    for (int o = 16; o > 0; o >>= 1) ss += __shfl_xor_sync(0xffffffffu, ss, o);
    float inv = 1.0f / fmaxf(sqrtf(ss), 1e-8f);
    uint32_t* dst = (uint32_t*)(g_zq + (size_t)row * D);
    dst[lid]      = pack_e4m3x4(a.x*inv, a.y*inv, a.z*inv, a.w*inv);
    dst[lid + 32] = pack_e4m3x4(b.x*inv, b.y*inv, b.z*inv, b.w*inv);
}

// ---------------------------------------------------------------------------
// Kernel 2: symmetric-exploiting fp8 sim GEMM.
// Grid 2080 = upper-triangular 128x128 tile pairs (I <= J).
// Each tile's exp values feed row-sums of block I (fragment rows) AND
// row-sums of block J (fragment columns, by symmetry). Diagonal tiles:
// row pass only, exact self-skip. Positive pairs live in tiles J == I+32.
// ---------------------------------------------------------------------------
__global__ void __launch_bounds__(THREADS, 2) sim_kernel() {
    __shared__ float rowsumArr[MT];
    __shared__ float colsumArr[MT];
    extern __shared__ char smem[];
    uint32_t sb = smem_u32(smem);

    int tid = threadIdx.x, wid = tid >> 5, lane = tid & 31;
    int rgw = wid & 3;          // warp row-group: rows rgw*32 .. +31
    int cg  = wid >> 2;         // warp col-group: cols cg*64 .. +63

    // ---- map blockIdx -> (I, J), I <= J, C(I) = I*(129-I)/2
    int t = blockIdx.x;
    int I = (int)(64.5f - sqrtf(64.5f * 64.5f - 2.0f * (float)t));
    if (I < 0) I = 0; if (I > 63) I = 63;
    while (I < 63 && (I + 1) * (128 - I) / 2 <= t) ++I;
    while (I > 0 && I * (129 - I) / 2 > t) --I;
    int J = I + (t - I * (129 - I) / 2);
    bool isDiag = (I == J), isPos = (J == I + 32);

    if (tid < MT) { rowsumArr[tid] = 0.f; colsumArr[tid] = 0.f; }

    // ---- load both panels (2048 16B-chunks each), swizzled 256B rows
    const char* gA = (const char*)(g_zq + (size_t)I * MT * D);
    const char* gB = (const char*)(g_zq + (size_t)J * MT * D);
    #pragma unroll
    for (int i = 0; i < 8; i++) {
        uint32_t c = i * 256 + tid, r = c >> 4, ch = c & 15;
        cp16(sb + SM_A + r * 256 + ((ch ^ (r & 7)) << 4), gA + (size_t)c * 16);
    }
    #pragma unroll
    for (int i = 0; i < 8; i++) {
        uint32_t c = i * 256 + tid, r = c >> 4, ch = c & 15;
        cp16(sb + SM_B + r * 256 + ((ch ^ (r & 7)) << 4), gB + (size_t)c * 16);
    }
    CP_COMMIT();
    CP_WAIT0();
    __syncthreads();

    // ---- per-lane ldsm addressing (fp8 m16n8k32 fragment order)
    uint32_t mm = lane >> 3, rr = lane & 7;
    uint32_t rsel  = (mm & 1) * 8 + rr;
    uint32_t cbase = mm >> 1;
    uint32_t aRow0 = rgw * 32 + rsel, aRow1 = aRow0 + 16;
    uint32_t aBase0 = sb + SM_A + aRow0 * 256, aSwz0 = aRow0 & 7;
    uint32_t aBase1 = sb + SM_A + aRow1 * 256, aSwz1 = aRow1 & 7;
    uint32_t bRow[4], bSwz[4];
    #pragma unroll
    for (int q = 0; q < 4; q++) {
        uint32_t br = cg * 64 + q * 16 + rsel;
        bRow[q] = br * 256; bSwz[q] = br & 7;
    }

    // ---- GEMM: warp tile m32 x n64, K = 8 steps of 32
    float acc[2][8][4];
    #pragma unroll
    for (int rg = 0; rg < 2; rg++)
        #pragma unroll
        for (int nb = 0; nb < 8; nb++)
            #pragma unroll
            for (int e = 0; e < 4; e++) acc[rg][nb][e] = 0.f;

    #pragma unroll
    for (int k = 0; k < 8; k++) {
        uint32_t ch = 2 * k + cbase;
        uint32_t a0[4], a1[4], b[4][4];
        ldsm4(a0, aBase0 + ((ch ^ aSwz0) << 4));
        ldsm4(a1, aBase1 + ((ch ^ aSwz1) << 4));
        #pragma unroll
        for (int q = 0; q < 4; q++)
            ldsm4(b[q], bRow[q] + sb + SM_B + ((ch ^ bSwz[q]) << 4));
        #pragma unroll
        for (int q = 0; q < 4; q++) {
            mma_fp8(acc[0][2*q],   a0, b[q][0], b[q][2]);
            mma_fp8(acc[0][2*q+1], a0, b[q][1], b[q][3]);
            mma_fp8(acc[1][2*q],   a1, b[q][0], b[q][2]);
            mma_fp8(acc[1][2*q+1], a1, b[q][1], b[q][3]);
        }
    }

    // ---- epilogue
    // fragment: row il = rgw*32 + (lane>>2) + rg*16 + 8*(e>>1)
    //           col jl = cg*64  + (lane&3)*2 + nb*8 + (e&1)
    int ilBase = rgw * 32 + (lane >> 2);
    int jlBase = cg * 64 + ((lane & 3) << 1);
    float rsum[2][2] = {{0.f,0.f},{0.f,0.f}};
    float colacc[8][2];
    #pragma unroll
    for (int nb = 0; nb < 8; nb++) { colacc[nb][0] = 0.f; colacc[nb][1] = 0.f; }

    if (!isDiag && !isPos) {
        #pragma unroll
        for (int rg = 0; rg < 2; rg++)
            #pragma unroll
            for (int nb = 0; nb < 8; nb++)
                #pragma unroll
                for (int e = 0; e < 4; e++) {
                    float v = __expf(2.f * acc[rg][nb][e]);
                    rsum[rg][e >> 1] += v;
                    colacc[nb][e & 1] += v;
                }
    } else {
        #pragma unroll
        for (int rg = 0; rg < 2; rg++)
            #pragma unroll
            for (int e = 0; e < 4; e++) {
                int il = ilBase + rg * 16 + 8 * (e >> 1);
                #pragma unroll
                for (int nb = 0; nb < 8; nb++) {
                    int jl = jlBase + nb * 8 + (e & 1);
                    float sim = 2.f * acc[rg][nb][e];
                    float v = __expf(sim);
                    if (isDiag && jl == il) v = 0.f;        // exact self-skip
                    if (isPos && jl == il) {                // positive pair
                        int gi = I * MT + il;
                        g_pos[gi] = sim; g_pos[gi + HALF_N] = sim;
                    }
                    rsum[rg][e >> 1] += v;
                    colacc[nb][e & 1] += v;
                }
            }
    }

    // row reduction: 4 lanes share a row
    #pragma unroll
    for (int rg = 0; rg < 2; rg++)
        #pragma unroll
        for (int h = 0; h < 2; h++) {
            float v = rsum[rg][h];
            v += __shfl_xor_sync(0xffffffffu, v, 1);
            v += __shfl_xor_sync(0xffffffffu, v, 2);
            if ((lane & 3) == 0)
                atomicAdd(&rowsumArr[ilBase + rg * 16 + 8 * h], v);
        }
    // column reduction: sum over the 8 row-lanes (strides 4, 8, 16)
    #pragma unroll
    for (int nb = 0; nb < 8; nb++)
        #pragma unroll
        for (int p = 0; p < 2; p++) {
            float v = colacc[nb][p];
            v += __shfl_xor_sync(0xffffffffu, v, 4);
            v += __shfl_xor_sync(0xffffffffu, v, 8);
            v += __shfl_xor_sync(0xffffffffu, v, 16);
            if (lane < 4)
                atomicAdd(&colsumArr[jlBase + nb * 8 + p], v);
        }
    __syncthreads();

    if (tid < MT)
        atomicAdd(&g_part[I * MT + tid], rowsumArr[tid]);
    else if (!isDiag)
        atomicAdd(&g_part[J * MT + (tid - MT)], colsumArr[tid - MT]);
}

// ---------------------------------------------------------------------------
// Kernel 3a: per-row loss, 32-block partial reduction.
// ---------------------------------------------------------------------------
__global__ void reduce1_kernel() {
    __shared__ float red[256];
    int r = blockIdx.x * 256 + threadIdx.x;
    red[threadIdx.x] = logf(g_part[r]) - g_pos[r];
    __syncthreads();
    #pragma unroll
    for (int k = 128; k > 0; k >>= 1) {
        if (threadIdx.x < k) red[threadIdx.x] += red[threadIdx.x + k];
        __syncthreads();
    }
    if (threadIdx.x == 0) g_blk[blockIdx.x] = red[0];
}
// Kernel 3b: final combine.
__global__ void reduce2_kernel(float* __restrict__ out) {
    float s = g_blk[threadIdx.x];
    #pragma unroll
    for (int o = 16; o > 0; o >>= 1) s += __shfl_xor_sync(0xffffffffu, s, o);
    if (threadIdx.x == 0) out[0] = s / (float)NROWS;
}

// ---------------------------------------------------------------------------
extern "C" void kernel_launch(void* const* d_in, const int* in_sizes, int n_in,
                              void* d_out, int out_size) {
    const float* z1 = (const float*)d_in[0];
    const float* z2 = (const float*)d_in[1];
    float* out = (float*)d_out;

    cudaFuncSetAttribute(sim_kernel,
                         cudaFuncAttributeMaxDynamicSharedMemorySize, SMEM_TOTAL);

    norm_kernel<<<NROWS / 8, 256>>>(z1, z2);
    sim_kernel<<<NTILES, THREADS, SMEM_TOTAL>>>();
    reduce1_kernel<<<32, 256>>>();
    reduce2_kernel<<<1, 32>>>(out);
}

// round 9
// speedup vs baseline: 2.2106x; 1.1287x over previous
#include <cuda_runtime.h>
#include <cuda_bf16.h>
#include <cstdint>

#define NROWS  8192
#define HALF_N 4096
#define D      256
#define MT     128
#define NTILES 2080           // 64*65/2 upper-triangular block pairs
#define THREADS 256

// fp8 panels: 128 rows x 256 B. A @0, B @32768.
#define SM_A  0
#define SM_B  32768
#define SMEM_TOTAL 65536

__device__ uint8_t g_zq[NROWS * D];   // normalized rows, e4m3 (2 MB, L2-resident)
__device__ float g_part[NROWS];       // per-row exp-sum (diag excluded), atomic accum
__device__ float g_pos[NROWS];        // per-row positive-pair logit

// ---------------------------------------------------------------------------
__device__ __forceinline__ uint32_t smem_u32(const void* p) {
    uint32_t a;
    asm("{ .reg .u64 t; cvta.to.shared.u64 t, %1; cvt.u32.u64 %0, t; }" : "=r"(a) : "l"(p));
    return a;
}
__device__ __forceinline__ void cp16(uint32_t dst, const void* src) {
    asm volatile("cp.async.cg.shared.global [%0], [%1], 16;" :: "r"(dst), "l"(src) : "memory");
}
#define CP_COMMIT() asm volatile("cp.async.commit_group;" ::: "memory")
#define CP_WAIT0()  asm volatile("cp.async.wait_group 0;" ::: "memory")

__device__ __forceinline__ void ldsm4(uint32_t* r, uint32_t addr) {
    asm volatile("ldmatrix.sync.aligned.m8n8.x4.shared.b16 {%0,%1,%2,%3}, [%4];"
        : "=r"(r[0]), "=r"(r[1]), "=r"(r[2]), "=r"(r[3]) : "r"(addr));
}
__device__ __forceinline__ void mma_fp8(float* c, const uint32_t* a,
                                        uint32_t b0, uint32_t b1) {
    asm volatile("mma.sync.aligned.m16n8k32.row.col.f32.e4m3.e4m3.f32 "
        "{%0,%1,%2,%3}, {%4,%5,%6,%7}, {%8,%9}, {%0,%1,%2,%3};"
        : "+f"(c[0]), "+f"(c[1]), "+f"(c[2]), "+f"(c[3])
        : "r"(a[0]), "r"(a[1]), "r"(a[2]), "r"(a[3]), "r"(b0), "r"(b1));
}
__device__ __forceinline__ uint32_t pack_e4m3x4(float x, float y, float z, float w) {
    uint16_t lo, hi;
    asm("cvt.rn.satfinite.e4m3x2.f32 %0, %1, %2;" : "=h"(lo) : "f"(y), "f"(x));
    asm("cvt.rn.satfinite.e4m3x2.f32 %0, %1, %2;" : "=h"(hi) : "f"(w), "f"(z));
    return (uint32_t)lo | ((uint32_t)hi << 16);
}

// ---------------------------------------------------------------------------
// Kernel 1: L2-normalize rows -> e4m3; also zero the accumulators.
// ---------------------------------------------------------------------------
__global__ void __launch_bounds__(256) norm_kernel(const float* __restrict__ z1,
                                                   const float* __restrict__ z2) {
    if (blockIdx.x < 32) {                       // zero g_part / g_pos
        int idx = blockIdx.x * 256 + threadIdx.x;
        g_part[idx] = 0.f; g_pos[idx] = 0.f;
    }
    int wid = threadIdx.x >> 5, lid = threadIdx.x & 31;
    int row = blockIdx.x * 8 + wid;
    const float* src = (row < HALF_N) ? z1 + (size_t)row * D
                                      : z2 + (size_t)(row - HALF_N) * D;
    const float4* s4 = (const float4*)src;
    float4 a = s4[lid], b = s4[lid + 32];
    float ss = a.x*a.x + a.y*a.y + a.z*a.z + a.w*a.w
             + b.x*b.x + b.y*b.y + b.z*b.z + b.w*b.w;
    #pragma unroll
    for (int o = 16; o > 0; o >>= 1) ss += __shfl_xor_sync(0xffffffffu, ss, o);
    float inv = 1.0f / fmaxf(sqrtf(ss), 1e-8f);
    uint32_t* dst = (uint32_t*)(g_zq + (size_t)row * D);
    dst[lid]      = pack_e4m3x4(a.x*inv, a.y*inv, a.z*inv, a.w*inv);
    dst[lid + 32] = pack_e4m3x4(b.x*inv, b.y*inv, b.z*inv, b.w*inv);
}

// ---------------------------------------------------------------------------
// Kernel 2: symmetric-exploiting fp8 sim GEMM (upper-triangular tile pairs).
// Row sums of block I from fragment rows; row sums of block J from fragment
// columns (symmetry). Non-atomic smem reduction: slices per warp-group.
// ---------------------------------------------------------------------------
__global__ void __launch_bounds__(THREADS, 2) sim_kernel() {
    __shared__ float rowsumArr[2][MT];           // sliced by cg
    __shared__ float colsumArr[4][MT];           // sliced by rgw
    extern __shared__ char smem[];
    uint32_t sb = smem_u32(smem);

    int tid = threadIdx.x, wid = tid >> 5, lane = tid & 31;
    int rgw = wid & 3;          // warp row-group: rows rgw*32 .. +31
    int cg  = wid >> 2;         // warp col-group: cols cg*64 .. +63

    // ---- map blockIdx -> (I, J), I <= J
    int t = blockIdx.x;
    int I = (int)(64.5f - sqrtf(64.5f * 64.5f - 2.0f * (float)t));
    if (I < 0) I = 0; if (I > 63) I = 63;
    while (I < 63 && (I + 1) * (128 - I) / 2 <= t) ++I;
    while (I > 0 && I * (129 - I) / 2 > t) --I;
    int J = I + (t - I * (129 - I) / 2);
    bool isDiag = (I == J), isPos = (J == I + 32);

    #pragma unroll
    for (int s = 0; s < 2; s++) if (tid < MT) rowsumArr[s][tid] = 0.f;
    #pragma unroll
    for (int s = 0; s < 4; s++) if (tid < MT) colsumArr[s][tid] = 0.f;

    // ---- load both panels (2048 16B-chunks each), swizzled 256B rows
    const char* gA = (const char*)(g_zq + (size_t)I * MT * D);
    const char* gB = (const char*)(g_zq + (size_t)J * MT * D);
    #pragma unroll
    for (int i = 0; i < 8; i++) {
        uint32_t c = i * 256 + tid, r = c >> 4, ch = c & 15;
        cp16(sb + SM_A + r * 256 + ((ch ^ (r & 7)) << 4), gA + (size_t)c * 16);
    }
    #pragma unroll
    for (int i = 0; i < 8; i++) {
        uint32_t c = i * 256 + tid, r = c >> 4, ch = c & 15;
        cp16(sb + SM_B + r * 256 + ((ch ^ (r & 7)) << 4), gB + (size_t)c * 16);
    }
    CP_COMMIT();
    CP_WAIT0();
    __syncthreads();

    // ---- per-lane ldsm addressing (fp8 m16n8k32 fragment order)
    uint32_t mm = lane >> 3, rr = lane & 7;
    uint32_t rsel  = (mm & 1) * 8 + rr;
    uint32_t cbase = mm >> 1;
    uint32_t aRow0 = rgw * 32 + rsel, aRow1 = aRow0 + 16;
    uint32_t aBase0 = sb + SM_A + aRow0 * 256, aSwz0 = aRow0 & 7;
    uint32_t aBase1 = sb + SM_A + aRow1 * 256, aSwz1 = aRow1 & 7;
    uint32_t bRow[4], bSwz[4];
    #pragma unroll
    for (int q = 0; q < 4; q++) {
        uint32_t br = cg * 64 + q * 16 + rsel;
        bRow[q] = br * 256; bSwz[q] = br & 7;
    }

    // ---- GEMM: warp tile m32 x n64, K = 8 steps of 32
    float acc[2][8][4];
    #pragma unroll
    for (int rg = 0; rg < 2; rg++)
        #pragma unroll
        for (int nb = 0; nb < 8; nb++)
            #pragma unroll
            for (int e = 0; e < 4; e++) acc[rg][nb][e] = 0.f;

    #pragma unroll
    for (int k = 0; k < 8; k++) {
        uint32_t ch = 2 * k + cbase;
        uint32_t a0[4], a1[4], b[4][4];
        ldsm4(a0, aBase0 + ((ch ^ aSwz0) << 4));
        ldsm4(a1, aBase1 + ((ch ^ aSwz1) << 4));
        #pragma unroll
        for (int q = 0; q < 4; q++)
            ldsm4(b[q], bRow[q] + sb + SM_B + ((ch ^ bSwz[q]) << 4));
        #pragma unroll
        for (int q = 0; q < 4; q++) {
            mma_fp8(acc[0][2*q],   a0, b[q][0], b[q][2]);
            mma_fp8(acc[0][2*q+1], a0, b[q][1], b[q][3]);
            mma_fp8(acc[1][2*q],   a1, b[q][0], b[q][2]);
            mma_fp8(acc[1][2*q+1], a1, b[q][1], b[q][3]);
        }
    }

    // ---- epilogue
    int ilBase = rgw * 32 + (lane >> 2);
    int jlBase = cg * 64 + ((lane & 3) << 1);
    float rsum[2][2] = {{0.f,0.f},{0.f,0.f}};
    float colacc[8][2];
    #pragma unroll
    for (int nb = 0; nb < 8; nb++) { colacc[nb][0] = 0.f; colacc[nb][1] = 0.f; }

    if (!isDiag && !isPos) {
        #pragma unroll
        for (int rg = 0; rg < 2; rg++)
            #pragma unroll
            for (int nb = 0; nb < 8; nb++)
                #pragma unroll
                for (int e = 0; e < 4; e++) {
                    float v = __expf(2.f * acc[rg][nb][e]);
                    rsum[rg][e >> 1] += v;
                    colacc[nb][e & 1] += v;
                }
    } else {
        #pragma unroll
        for (int rg = 0; rg < 2; rg++)
            #pragma unroll
            for (int e = 0; e < 4; e++) {
                int il = ilBase + rg * 16 + 8 * (e >> 1);
                #pragma unroll
                for (int nb = 0; nb < 8; nb++) {
                    int jl = jlBase + nb * 8 + (e & 1);
                    float sim = 2.f * acc[rg][nb][e];
                    float v = __expf(sim);
                    if (isDiag && jl == il) v = 0.f;        // exact self-skip
                    if (isPos && jl == il) {                // positive pair
                        int gi = I * MT + il;
                        g_pos[gi] = sim; g_pos[gi + HALF_N] = sim;
                    }
                    rsum[rg][e >> 1] += v;
                    colacc[nb][e & 1] += v;
                }
            }
    }

    // row reduction: 4 lanes share a row; write to cg-slice (no atomics)
    #pragma unroll
    for (int rg = 0; rg < 2; rg++)
        #pragma unroll
        for (int h = 0; h < 2; h++) {
            float v = rsum[rg][h];
            v += __shfl_xor_sync(0xffffffffu, v, 1);
            v += __shfl_xor_sync(0xffffffffu, v, 2);
            if ((lane & 3) == 0)
                rowsumArr[cg][ilBase + rg * 16 + 8 * h] = v;
        }
    // column reduction: sum the 8 row-lanes; write to rgw-slice (no atomics)
    #pragma unroll
    for (int nb = 0; nb < 8; nb++)
        #pragma unroll
        for (int p = 0; p < 2; p++) {
            float v = colacc[nb][p];
            v += __shfl_xor_sync(0xffffffffu, v, 4);
            v += __shfl_xor_sync(0xffffffffu, v, 8);
            v += __shfl_xor_sync(0xffffffffu, v, 16);
            if (lane < 4)
                colsumArr[rgw][jlBase + nb * 8 + p] = v;
        }
    __syncthreads();

    if (tid < MT) {
        atomicAdd(&g_part[I * MT + tid], rowsumArr[0][tid] + rowsumArr[1][tid]);
    } else if (!isDiag) {
        int r = tid - MT;
        atomicAdd(&g_part[J * MT + r],
                  (colsumArr[0][r] + colsumArr[1][r]) +
                  (colsumArr[2][r] + colsumArr[3][r]));
    }
}

// ---------------------------------------------------------------------------
// Kernel 3: single-block fused per-row loss + mean.
// ---------------------------------------------------------------------------
__global__ void __launch_bounds__(1024) reduce_kernel(float* __restrict__ out) {
    __shared__ float red[1024];
    int t = threadIdx.x;
    float s = 0.0f;
    #pragma unroll
    for (int i = 0; i < 8; i++) {
        int r = t + i * 1024;
        s += logf(g_part[r]) - g_pos[r];
    }
    red[t] = s;
    __syncthreads();
    #pragma unroll
    for (int k = 512; k > 0; k >>= 1) {
        if (t < k) red[t] += red[t + k];
        __syncthreads();
    }
    if (t == 0) out[0] = red[0] / (float)NROWS;
}

// ---------------------------------------------------------------------------
extern "C" void kernel_launch(void* const* d_in, const int* in_sizes, int n_in,
                              void* d_out, int out_size) {
    const float* z1 = (const float*)d_in[0];
    const float* z2 = (const float*)d_in[1];
    float* out = (float*)d_out;

    cudaFuncSetAttribute(sim_kernel,
                         cudaFuncAttributeMaxDynamicSharedMemorySize, SMEM_TOTAL);

    norm_kernel<<<NROWS / 8, 256>>>(z1, z2);
    sim_kernel<<<NTILES, THREADS, SMEM_TOTAL>>>();
    reduce_kernel<<<1, 1024>>>(out);
}